// round 3
// baseline (speedup 1.0000x reference)
#include <cuda_runtime.h>
#include <math.h>

#define SIZE 1000

// ---------------------------------------------------------------------------
// Kernel 1: zero the [1000,1000,10] fp32 output (40 MB) with float4 stores.
// This is the HBM roofline term: ~40MB write-only.
// ---------------------------------------------------------------------------
__global__ void vi_zero_kernel(float4* __restrict__ out, int n4) {
    int i = blockIdx.x * blockDim.x + threadIdx.x;
    if (i < n4) out[i] = make_float4(0.f, 0.f, 0.f, 0.f);
}

// ---------------------------------------------------------------------------
// tanh(100000 * x), exploiting exact fp32 saturation:
//   1 - tanh(t) = 2e^{-2t} < 2^-25 (half-ulp of 1.0f) for t > 9.02,
// so tanhf(t) rounds to exactly +/-1.0f whenever |x| >= 1e-4 (t >= 10).
// Fast path is a compare + copysign; the true tanhf is kept only for the
// tiny non-saturated band so the math stays bit-faithful in all cases.
// ---------------------------------------------------------------------------
__device__ __forceinline__ float vi_sgn(float x) {
    if (fabsf(x) >= 1e-4f) return copysignf(1.0f, x);
    return tanhf(100000.0f * x);
}

// ---------------------------------------------------------------------------
// Exact per-element mask value (pre-transpose coords i=row, j=col):
//   x1 = T(a-j),  y1 = T(b-(i+1)),  x3 = T(a-(j+1)),  y3 = T(b-i)
//   mask = T(y1*x1) * T(y3*x3);  return (1-mask)/2   where T = tanh(1e5*.)
// ---------------------------------------------------------------------------
__device__ __forceinline__ float vi_maskval(float a, float b, int i, int j) {
    float x1 = vi_sgn(a - (float)j);
    float y1 = vi_sgn(b - (float)(i + 1));
    float x3 = vi_sgn(a - (float)(j + 1));
    float y3 = vi_sgn(b - (float)i);
    float m1 = vi_sgn(y1 * x1);
    float m3 = vi_sgn(y3 * x3);
    return (1.0f - m1 * m3) * 0.5f;
}

// Transposed mask with zero padding: mask_t(p,q) = mask(i=q, j=p)
__device__ __forceinline__ float vi_mt(float a, float b, int p, int q) {
    if (p < 0 || p >= SIZE || q < 0 || q >= SIZE) return 0.0f;
    return vi_maskval(a, b, q, p);
}

// ---------------------------------------------------------------------------
// Kernel 2: for each of the 8 input points, evaluate relu(plus_conv - 3) on a
// 7x7 window around (floor(a), floor(b)) — all nonzeros of the full result
// live within +/-2 cells of that point. Scatter-max into out[p,q,cls].
// atomicMax on int bits is exact for non-negative floats.
// ---------------------------------------------------------------------------
__global__ void vi_point_kernel(const float* __restrict__ z_pos,
                                const int* __restrict__ z_cls,
                                float* __restrict__ out) {
    int n = blockIdx.x;      // 8 blocks, one per input point
    int t = threadIdx.x;     // 49 threads = 7x7 window
    float a = z_pos[2 * n + 0] * 1000.0f;
    float b = z_pos[2 * n + 1] * 1000.0f;
    int jc = (int)floorf(a);
    int ic = (int)floorf(b);

    int p = jc + (t % 7) - 3;
    int q = ic + (t / 7) - 3;
    if (p < 0 || p >= SIZE || q < 0 || q >= SIZE) return;

    // plus-shaped 3x3 conv, SAME padding (zeros), on transposed mask
    float conv = vi_mt(a, b, p - 1, q) + vi_mt(a, b, p + 1, q) +
                 vi_mt(a, b, p, q - 1) + vi_mt(a, b, p, q + 1);
    float v = conv - 3.0f;   // relu
    if (v <= 0.0f) return;

    int c = z_cls[n];        // one-hot class channel
    atomicMax((int*)&out[((long long)p * SIZE + q) * 10 + c], __float_as_int(v));
}

extern "C" void kernel_launch(void* const* d_in, const int* in_sizes, int n_in,
                              void* d_out, int out_size) {
    const float* z_pos = (const float*)d_in[0];  // [8,2] fp32
    const int* z_cls = (const int*)d_in[1];      // [8] int32
    float* out = (float*)d_out;                  // [1000,1000,10] fp32

    int n4 = out_size / 4;                       // 2,500,000 float4s
    vi_zero_kernel<<<(n4 + 255) / 256, 256>>>((float4*)out, n4);
    vi_point_kernel<<<8, 49>>>(z_pos, z_cls, out);
}

// round 4
// speedup vs baseline: 1.3113x; 1.3113x over previous
#include <cuda_runtime.h>
#include <math.h>

#define SIZE 1000

// ---------------------------------------------------------------------------
// Kernel 1: zero the [1000,1000,10] fp32 output (40 MB) with float4 stores.
// This is the HBM roofline term: ~40MB write-only.
// ---------------------------------------------------------------------------
__global__ void vi_zero_kernel(float4* __restrict__ out, int n4) {
    int i = blockIdx.x * blockDim.x + threadIdx.x;
    if (i < n4) out[i] = make_float4(0.f, 0.f, 0.f, 0.f);
}

// ---------------------------------------------------------------------------
// tanh(100000 * x), exploiting exact fp32 saturation:
//   1 - tanh(t) = 2e^{-2t} < 2^-25 (half-ulp of 1.0f) for t > 9.02,
// so tanhf(t) rounds to exactly +/-1.0f whenever |x| >= 1e-4 (t >= 10).
// Fast path is a compare + copysign; the true tanhf is kept only for the
// tiny non-saturated band so the math stays bit-faithful in all cases.
// ---------------------------------------------------------------------------
__device__ __forceinline__ float vi_sgn(float x) {
    if (fabsf(x) >= 1e-4f) return copysignf(1.0f, x);
    return tanhf(100000.0f * x);
}

// ---------------------------------------------------------------------------
// Exact per-element mask value (pre-transpose coords i=row, j=col):
//   x1 = T(a-j),  y1 = T(b-(i+1)),  x3 = T(a-(j+1)),  y3 = T(b-i)
//   mask = T(y1*x1) * T(y3*x3);  return (1-mask)/2   where T = tanh(1e5*.)
// ---------------------------------------------------------------------------
__device__ __forceinline__ float vi_maskval(float a, float b, int i, int j) {
    float x1 = vi_sgn(a - (float)j);
    float y1 = vi_sgn(b - (float)(i + 1));
    float x3 = vi_sgn(a - (float)(j + 1));
    float y3 = vi_sgn(b - (float)i);
    float m1 = vi_sgn(y1 * x1);
    float m3 = vi_sgn(y3 * x3);
    return (1.0f - m1 * m3) * 0.5f;
}

// Transposed mask with zero padding: mask_t(p,q) = mask(i=q, j=p)
__device__ __forceinline__ float vi_mt(float a, float b, int p, int q) {
    if (p < 0 || p >= SIZE || q < 0 || q >= SIZE) return 0.0f;
    return vi_maskval(a, b, q, p);
}

// ---------------------------------------------------------------------------
// Kernel 2: for each of the 8 input points, evaluate relu(plus_conv - 3) on a
// 7x7 window around (floor(a), floor(b)) — all nonzeros of the full result
// live within +/-2 cells of that point. Scatter-max into out[p,q,cls].
// atomicMax on int bits is exact for non-negative floats.
// ---------------------------------------------------------------------------
__global__ void vi_point_kernel(const float* __restrict__ z_pos,
                                const int* __restrict__ z_cls,
                                float* __restrict__ out) {
    int n = blockIdx.x;      // 8 blocks, one per input point
    int t = threadIdx.x;     // 49 threads = 7x7 window
    float a = z_pos[2 * n + 0] * 1000.0f;
    float b = z_pos[2 * n + 1] * 1000.0f;
    int jc = (int)floorf(a);
    int ic = (int)floorf(b);

    int p = jc + (t % 7) - 3;
    int q = ic + (t / 7) - 3;
    if (p < 0 || p >= SIZE || q < 0 || q >= SIZE) return;

    // plus-shaped 3x3 conv, SAME padding (zeros), on transposed mask
    float conv = vi_mt(a, b, p - 1, q) + vi_mt(a, b, p + 1, q) +
                 vi_mt(a, b, p, q - 1) + vi_mt(a, b, p, q + 1);
    float v = conv - 3.0f;   // relu
    if (v <= 0.0f) return;

    int c = z_cls[n];        // one-hot class channel
    atomicMax((int*)&out[((long long)p * SIZE + q) * 10 + c], __float_as_int(v));
}

extern "C" void kernel_launch(void* const* d_in, const int* in_sizes, int n_in,
                              void* d_out, int out_size) {
    const float* z_pos = (const float*)d_in[0];  // [8,2] fp32
    const int* z_cls = (const int*)d_in[1];      // [8] int32
    float* out = (float*)d_out;                  // [1000,1000,10] fp32

    int n4 = out_size / 4;                       // 2,500,000 float4s
    vi_zero_kernel<<<(n4 + 255) / 256, 256>>>((float4*)out, n4);
    vi_point_kernel<<<8, 49>>>(z_pos, z_cls, out);
}

// round 5
// speedup vs baseline: 1.3375x; 1.0200x over previous
#include <cuda_runtime.h>
#include <math.h>

#define SIZE 1000

// ---------------------------------------------------------------------------
// Kernel 1: zero the [1000,1000,10] fp32 output (40 MB) with float4 stores.
// This is the HBM roofline term: ~40MB write-only.
// ---------------------------------------------------------------------------
__global__ void vi_zero_kernel(float4* __restrict__ out, int n4) {
    int i = blockIdx.x * blockDim.x + threadIdx.x;
    if (i < n4) out[i] = make_float4(0.f, 0.f, 0.f, 0.f);
}

// ---------------------------------------------------------------------------
// tanh(100000 * x), exploiting exact fp32 saturation:
//   1 - tanh(t) = 2e^{-2t} < 2^-25 (half-ulp of 1.0f) for t > 9.02,
// so tanhf(t) rounds to exactly +/-1.0f whenever |x| >= 1e-4 (t >= 10).
// Fast path is a compare + copysign; the true tanhf is kept only for the
// tiny non-saturated band so the math stays bit-faithful in all cases.
// ---------------------------------------------------------------------------
__device__ __forceinline__ float vi_sgn(float x) {
    if (fabsf(x) >= 1e-4f) return copysignf(1.0f, x);
    return tanhf(100000.0f * x);
}

// ---------------------------------------------------------------------------
// Exact per-element mask value (pre-transpose coords i=row, j=col):
//   x1 = T(a-j),  y1 = T(b-(i+1)),  x3 = T(a-(j+1)),  y3 = T(b-i)
//   mask = T(y1*x1) * T(y3*x3);  return (1-mask)/2   where T = tanh(1e5*.)
// ---------------------------------------------------------------------------
__device__ __forceinline__ float vi_maskval(float a, float b, int i, int j) {
    float x1 = vi_sgn(a - (float)j);
    float y1 = vi_sgn(b - (float)(i + 1));
    float x3 = vi_sgn(a - (float)(j + 1));
    float y3 = vi_sgn(b - (float)i);
    float m1 = vi_sgn(y1 * x1);
    float m3 = vi_sgn(y3 * x3);
    return (1.0f - m1 * m3) * 0.5f;
}

// Transposed mask with zero padding: mask_t(p,q) = mask(i=q, j=p)
__device__ __forceinline__ float vi_mt(float a, float b, int p, int q) {
    if (p < 0 || p >= SIZE || q < 0 || q >= SIZE) return 0.0f;
    return vi_maskval(a, b, q, p);
}

// ---------------------------------------------------------------------------
// Kernel 2: for each of the 8 input points, evaluate relu(plus_conv - 3) on a
// 7x7 window around (floor(a), floor(b)) — all nonzeros of the full result
// live within +/-2 cells of that point. Scatter-max into out[p,q,cls].
// atomicMax on int bits is exact for non-negative floats.
// ---------------------------------------------------------------------------
__global__ void vi_point_kernel(const float* __restrict__ z_pos,
                                const int* __restrict__ z_cls,
                                float* __restrict__ out) {
    int n = blockIdx.x;      // 8 blocks, one per input point
    int t = threadIdx.x;     // 49 threads = 7x7 window
    float a = z_pos[2 * n + 0] * 1000.0f;
    float b = z_pos[2 * n + 1] * 1000.0f;
    int jc = (int)floorf(a);
    int ic = (int)floorf(b);

    int p = jc + (t % 7) - 3;
    int q = ic + (t / 7) - 3;
    if (p < 0 || p >= SIZE || q < 0 || q >= SIZE) return;

    // plus-shaped 3x3 conv, SAME padding (zeros), on transposed mask
    float conv = vi_mt(a, b, p - 1, q) + vi_mt(a, b, p + 1, q) +
                 vi_mt(a, b, p, q - 1) + vi_mt(a, b, p, q + 1);
    float v = conv - 3.0f;   // relu
    if (v <= 0.0f) return;

    int c = z_cls[n];        // one-hot class channel
    atomicMax((int*)&out[((long long)p * SIZE + q) * 10 + c], __float_as_int(v));
}

extern "C" void kernel_launch(void* const* d_in, const int* in_sizes, int n_in,
                              void* d_out, int out_size) {
    const float* z_pos = (const float*)d_in[0];  // [8,2] fp32
    const int* z_cls = (const int*)d_in[1];      // [8] int32
    float* out = (float*)d_out;                  // [1000,1000,10] fp32

    int n4 = out_size / 4;                       // 2,500,000 float4s
    vi_zero_kernel<<<(n4 + 255) / 256, 256>>>((float4*)out, n4);
    vi_point_kernel<<<8, 49>>>(z_pos, z_cls, out);
}